// round 9
// baseline (speedup 1.0000x reference)
#include <cuda_runtime.h>
#include <math.h>
#include <float.h>

#define N_PTS 32768
#define C_IN 6
#define H_DIM 64
#define M_PTS 8192
#define KF 32
#define KN 16
#define KS 8
#define SPLIT 4
#define CRANGE (M_PTS / SPLIT)   // 2048 candidates per partial CTA
#define CAP 64

// ---------------- scratch (no dynamic allocation allowed) ----------------
__device__ float  g_z1[N_PTS * H_DIM];
__device__ float  g_z2[N_PTS * H_DIM];
__device__ float  g_s[N_PTS];
__device__ float  g_bn[4 * H_DIM];
__device__ double g_acc[6];
__device__ float  g_pd[SPLIT * KF * N_PTS];  // partial dists (v-space), [sp][k][q]
__device__ int    g_pi[SPLIT * KF * N_PTS];  // partial indices,        [sp][k][q]

__global__ void k_zero() {
    int t = threadIdx.x;
    if (t < 4 * H_DIM) g_bn[t] = 0.0f;
    if (t < 6) g_acc[t] = 0.0;
}

__device__ __forceinline__ float gelu_exact(float x) {
    return 0.5f * x * (1.0f + erff(x * 0.70710678118654752f));
}

// sorted top-32 insert (strict < => earlier/lower-index wins ties, matches top_k)
__device__ __forceinline__ void insert32(float (&dist)[KF], int (&idx)[KF],
                                         float cd, int ci) {
#pragma unroll
    for (int k = 0; k < KF; k++) {
        bool p = cd < dist[k];
        float nd = p ? cd : dist[k];
        float xd = p ? dist[k] : cd;
        int   ni = p ? ci : idx[k];
        int   xi = p ? idx[k] : ci;
        dist[k] = nd; cd = xd;
        idx[k]  = ni; ci = xi;
    }
}

// ---------------- MLP stage 1 ----------------
__global__ void k_mlp1(const float* __restrict__ feat,
                       const float* __restrict__ W1,
                       const float* __restrict__ b1) {
    __shared__ float sW[C_IN * H_DIM];
    __shared__ float sb[H_DIM];
    __shared__ float s_sum[H_DIM], s_sq[H_DIM];
    int t = threadIdx.x;
    for (int i = t; i < C_IN * H_DIM; i += blockDim.x) sW[i] = W1[i];
    if (t < H_DIM) { sb[t] = b1[t]; s_sum[t] = 0.0f; s_sq[t] = 0.0f; }
    __syncthreads();

    int row = blockIdx.x * blockDim.x + t;
    float f[C_IN];
#pragma unroll
    for (int c = 0; c < C_IN; c++) f[c] = feat[row * C_IN + c];

    int lane = t & 31;
#pragma unroll
    for (int h = 0; h < H_DIM; h++) {
        float a = sb[h];
#pragma unroll
        for (int c = 0; c < C_IN; c++) a = fmaf(f[c], sW[c * H_DIM + h], a);
        g_z1[h * N_PTS + row] = a;
        float v = a, v2 = a * a;
#pragma unroll
        for (int o = 16; o; o >>= 1) {
            v  += __shfl_down_sync(0xffffffffu, v,  o);
            v2 += __shfl_down_sync(0xffffffffu, v2, o);
        }
        if (lane == 0) { atomicAdd(&s_sum[h], v); atomicAdd(&s_sq[h], v2); }
    }
    __syncthreads();
    if (t < H_DIM) {
        atomicAdd(&g_bn[t], s_sum[t]);
        atomicAdd(&g_bn[H_DIM + t], s_sq[t]);
    }
}

// ---------------- MLP stage 2 ----------------
__global__ void k_mlp2(const float* __restrict__ W2,
                       const float* __restrict__ b2,
                       const float* __restrict__ g1,
                       const float* __restrict__ be1) {
    __shared__ float sW[H_DIM * H_DIM];
    __shared__ float s_mu[H_DIM], s_rs[H_DIM], s_g[H_DIM], s_be[H_DIM], s_b2[H_DIM];
    __shared__ float s_sum[H_DIM], s_sq[H_DIM];
    int t = threadIdx.x;
    for (int i = t; i < H_DIM * H_DIM; i += blockDim.x) sW[i] = W2[i];
    if (t < H_DIM) {
        float mu  = g_bn[t] * (1.0f / N_PTS);
        float var = g_bn[H_DIM + t] * (1.0f / N_PTS) - mu * mu;
        s_mu[t] = mu;
        s_rs[t] = rsqrtf(var + 1e-5f);
        s_g[t] = g1[t]; s_be[t] = be1[t]; s_b2[t] = b2[t];
        s_sum[t] = 0.0f; s_sq[t] = 0.0f;
    }
    __syncthreads();

    int row = blockIdx.x * blockDim.x + t;
    float h1[H_DIM];
#pragma unroll
    for (int h = 0; h < H_DIM; h++) {
        float x = g_z1[h * N_PTS + row];
        x = s_g[h] * (x - s_mu[h]) * s_rs[h] + s_be[h];
        h1[h] = gelu_exact(x);
    }

    int lane = t & 31;
    for (int j = 0; j < H_DIM; j++) {
        float acc = s_b2[j];
#pragma unroll
        for (int h = 0; h < H_DIM; h++) acc = fmaf(h1[h], sW[h * H_DIM + j], acc);
        g_z2[j * N_PTS + row] = acc;
        float v = acc, v2 = acc * acc;
#pragma unroll
        for (int o = 16; o; o >>= 1) {
            v  += __shfl_down_sync(0xffffffffu, v,  o);
            v2 += __shfl_down_sync(0xffffffffu, v2, o);
        }
        if (lane == 0) { atomicAdd(&s_sum[j], v); atomicAdd(&s_sq[j], v2); }
    }
    __syncthreads();
    if (t < H_DIM) {
        atomicAdd(&g_bn[2 * H_DIM + t], s_sum[t]);
        atomicAdd(&g_bn[3 * H_DIM + t], s_sq[t]);
    }
}

// ---------------- MLP stage 3 ----------------
__global__ void k_mlp3(const float* __restrict__ W3,
                       const float* __restrict__ b3,
                       const float* __restrict__ g2,
                       const float* __restrict__ be2) {
    __shared__ float s_mu[H_DIM], s_rs[H_DIM], s_g[H_DIM], s_be[H_DIM], s_w3[H_DIM];
    __shared__ float s_b3;
    int t = threadIdx.x;
    if (t < H_DIM) {
        float mu  = g_bn[2 * H_DIM + t] * (1.0f / N_PTS);
        float var = g_bn[3 * H_DIM + t] * (1.0f / N_PTS) - mu * mu;
        s_mu[t] = mu;
        s_rs[t] = rsqrtf(var + 1e-5f);
        s_g[t] = g2[t]; s_be[t] = be2[t]; s_w3[t] = W3[t];
    }
    if (t == 0) s_b3 = b3[0];
    __syncthreads();

    int row = blockIdx.x * blockDim.x + t;
    float acc = s_b3;
#pragma unroll
    for (int h = 0; h < H_DIM; h++) {
        float x = g_z2[h * N_PTS + row];
        x = s_g[h] * (x - s_mu[h]) * s_rs[h] + s_be[h];
        x = gelu_exact(x);
        acc = fmaf(x, s_w3[h], acc);
    }
    g_s[row] = 1.0f / (1.0f + expf(-acc));
}

// ---------------- KNN partial: top-32 over a 2048-candidate slice ----------------
// v = ||c||^2 - 2 q.c = d2 - ||q||^2  (monotone in d2 per query; same formula
// family as the reference's sq[:,None]+sq[None,:]-2c@cT selection)
__global__ void __launch_bounds__(256, 2)
k_knn_part(const float* __restrict__ coords) {
    __shared__ float4 sc[CRANGE];

    int t = threadIdx.x;
    int qb = blockIdx.x & 127;          // query block 0..127
    int sp = blockIdx.x >> 7;           // split 0..3
    int qi = qb * 256 + t;
    int scene_base = qi & ~(M_PTS - 1);
    int cand_base = scene_base + sp * CRANGE;

    // stage candidate slice with precomputed norm in .w
    for (int i = t; i < CRANGE; i += 256) {
        int g = (cand_base + i) * 3;
        float x = coords[g], y = coords[g + 1], z = coords[g + 2];
        sc[i] = make_float4(x, y, z, fmaf(x, x, fmaf(y, y, z * z)));
    }
    __syncthreads();

    float qx = coords[qi * 3 + 0];
    float qy = coords[qi * 3 + 1];
    float qz = coords[qi * 3 + 2];
    float ax = -2.0f * qx, ay = -2.0f * qy, az = -2.0f * qz;

    float dist[KF];
    int   idx[KF];
#pragma unroll
    for (int k = 0; k < KF; k++) { dist[k] = FLT_MAX; idx[k] = 0; }

    // boot: first 32 candidates establish tau
#pragma unroll
    for (int cc = 0; cc < 32; cc++) {
        float4 p = sc[cc];
        float v = fmaf(ax, p.x, fmaf(ay, p.y, fmaf(az, p.z, p.w)));
        insert32(dist, idx, v, cand_base + cc);
    }
    float tau = dist[KF - 1];

    float buf_d[CAP];
    int   buf_i[CAP];
    int   cnt = 0;

    for (int chunk = 32; chunk < CRANGE; chunk += 32) {
#pragma unroll
        for (int cc = 0; cc < 32; cc++) {
            float4 p = sc[chunk + cc];
            float v = fmaf(ax, p.x, fmaf(ay, p.y, fmaf(az, p.z, p.w)));
            if (v < tau) {
                buf_d[cnt] = v;
                buf_i[cnt] = cand_base + chunk + cc;
                cnt++;
            }
        }
        if (__any_sync(0xffffffffu, cnt > CAP - 32)) {
            for (int j = 0; j < cnt; j++) {
                float cd = buf_d[j];
                if (cd < dist[KF - 1]) insert32(dist, idx, cd, buf_i[j]);
            }
            cnt = 0;
            tau = dist[KF - 1];
        }
    }
    for (int j = 0; j < cnt; j++) {
        float cd = buf_d[j];
        if (cd < dist[KF - 1]) insert32(dist, idx, cd, buf_i[j]);
    }

    // coalesced partial store: [sp][k][q]
#pragma unroll
    for (int k = 0; k < KF; k++) {
        g_pd[(sp * KF + k) * N_PTS + qi] = dist[k];
        g_pi[(sp * KF + k) * N_PTS + qi] = idx[k];
    }
}

// ---------------- merge partials + fused loss ----------------
__global__ void __launch_bounds__(256)
k_merge(const float* __restrict__ coords) {
    __shared__ float s_red[8 * 5];
    int t = threadIdx.x;
    int qi = blockIdx.x * 256 + t;

    float dist[KF];
    int   idx[KF];
#pragma unroll
    for (int k = 0; k < KF; k++) {
        dist[k] = g_pd[k * N_PTS + qi];
        idx[k]  = g_pi[k * N_PTS + qi];
    }
    // merge splits 1..3 (ascending index ranges; strict < keeps earlier split
    // on ties => lower index => matches stable top_k). Sorted-stream early break
    // is safe: dist[31] only decreases.
    for (int sp = 1; sp < SPLIT; sp++) {
        for (int j = 0; j < KF; j++) {
            float v = g_pd[(sp * KF + j) * N_PTS + qi];
            if (v >= dist[KF - 1]) break;
            insert32(dist, idx, v, g_pi[(sp * KF + j) * N_PTS + qi]);
        }
    }

    // ---- fused loss (exact diff-form d2 for near neighbors) ----
    float qx = coords[qi * 3 + 0];
    float qy = coords[qi * 3 + 1];
    float qz = coords[qi * 3 + 2];
    float si = g_s[qi];
    float num = 0.0f, den = 0.0f, lp = 0.0f, ln_ = 0.0f, nm = 0.0f;

#pragma unroll
    for (int k = 0; k < KN; k++) {
        int j = idx[k];
        float sj = g_s[j];
        float ad = fabsf(si - sj);
        float dx = qx - coords[j * 3 + 0];
        float dy = qy - coords[j * 3 + 1];
        float dz = qz - coords[j * 3 + 2];
        float d2 = fmaf(dz, dz, fmaf(dy, dy, dx * dx));
        float d  = sqrtf(fmaxf(d2, 1e-24f));
        float w  = expf(-d * 10.0f);                   // 1 / T_LOC
        num = fmaf(w * ad, ad, num);
        den += w;
        float simp = 1.0f - ad;
        float sg = 1.0f / (1.0f + expf(-2.0f * simp)); // / T_CON
        lp += logf(sg + 1e-8f);
        if (k < KS) nm += sj;
    }
#pragma unroll
    for (int k = KN; k < KF; k++) {
        float sj = g_s[idx[k]];
        float ad = fabsf(si - sj);
        float simn = 1.0f - ad;
        float sg = 1.0f / (1.0f + expf(-2.0f * simn));
        ln_ += logf(1.0f - sg + 1e-8f);
    }
    nm *= (1.0f / KS);
    float sm = (si - nm) * (si - nm);

    int lane = t & 31, wid = t >> 5;
    float v0 = num, v1 = den, v2 = lp, v3 = ln_, v4 = sm;
#pragma unroll
    for (int o = 16; o; o >>= 1) {
        v0 += __shfl_down_sync(0xffffffffu, v0, o);
        v1 += __shfl_down_sync(0xffffffffu, v1, o);
        v2 += __shfl_down_sync(0xffffffffu, v2, o);
        v3 += __shfl_down_sync(0xffffffffu, v3, o);
        v4 += __shfl_down_sync(0xffffffffu, v4, o);
    }
    if (lane == 0) {
        s_red[wid * 5 + 0] = v0; s_red[wid * 5 + 1] = v1;
        s_red[wid * 5 + 2] = v2; s_red[wid * 5 + 3] = v3;
        s_red[wid * 5 + 4] = v4;
    }
    __syncthreads();
    if (t == 0) {
        double a0 = 0, a1 = 0, a2 = 0, a3 = 0, a4 = 0;
#pragma unroll
        for (int w = 0; w < 8; w++) {
            a0 += (double)s_red[w * 5 + 0];
            a1 += (double)s_red[w * 5 + 1];
            a2 += (double)s_red[w * 5 + 2];
            a3 += (double)s_red[w * 5 + 3];
            a4 += (double)s_red[w * 5 + 4];
        }
        atomicAdd(&g_acc[0], a0);
        atomicAdd(&g_acc[1], a1);
        atomicAdd(&g_acc[2], a2);
        atomicAdd(&g_acc[3], a3);
        atomicAdd(&g_acc[4], a4);
    }
}

__global__ void k_fin(float* __restrict__ out) {
    if (threadIdx.x == 0) {
        double loc = g_acc[0] / fmax(g_acc[1], 1e-8);
        double inv = 1.0 / ((double)N_PTS * (double)KN);
        double pos = -g_acc[2] * inv;
        double neg = -g_acc[3] * inv;
        double sm  = g_acc[4] / (double)N_PTS;
        out[0] = (float)(loc + 0.5 * (pos + neg) + 0.2 * sm);
    }
}

// ---------------- launch ----------------
extern "C" void kernel_launch(void* const* d_in, const int* in_sizes, int n_in,
                              void* d_out, int out_size) {
    const float* feat   = (const float*)d_in[0];
    const float* coords = (const float*)d_in[1];
    const float* W1 = (const float*)d_in[2];
    const float* b1 = (const float*)d_in[3];
    const float* g1 = (const float*)d_in[4];
    const float* be1 = (const float*)d_in[5];
    const float* W2 = (const float*)d_in[6];
    const float* b2 = (const float*)d_in[7];
    const float* g2 = (const float*)d_in[8];
    const float* be2 = (const float*)d_in[9];
    const float* W3 = (const float*)d_in[10];
    const float* b3 = (const float*)d_in[11];
    float* out = (float*)d_out;

    k_zero<<<1, 256>>>();
    k_mlp1<<<N_PTS / 256, 256>>>(feat, W1, b1);
    k_mlp2<<<N_PTS / 256, 256>>>(W2, b2, g1, be1);
    k_mlp3<<<N_PTS / 256, 256>>>(W3, b3, g2, be2);
    k_knn_part<<<SPLIT * (N_PTS / 256), 256>>>(coords);
    k_merge<<<N_PTS / 256, 256>>>(coords);
    k_fin<<<1, 1>>>(out);
}

// round 10
// speedup vs baseline: 1.9427x; 1.9427x over previous
#include <cuda_runtime.h>
#include <math.h>
#include <float.h>

#define N_PTS 32768
#define C_IN 6
#define H_DIM 64
#define M_PTS 8192
#define KF 32
#define KN 16
#define KS 8
#define TILE 2048
#define CAP 64
#define KNN_BLK 128

// ---------------- scratch (no dynamic allocation allowed) ----------------
__device__ float  g_z1[N_PTS * H_DIM];
__device__ float  g_z2[N_PTS * H_DIM];
__device__ float  g_s[N_PTS];
__device__ float  g_bn[4 * H_DIM];
__device__ double g_acc[6];

__global__ void k_zero() {
    int t = threadIdx.x;
    if (t < 4 * H_DIM) g_bn[t] = 0.0f;
    if (t < 6) g_acc[t] = 0.0;
}

__device__ __forceinline__ float gelu_exact(float x) {
    return 0.5f * x * (1.0f + erff(x * 0.70710678118654752f));
}

// sorted top-32 insert (strict < => earlier/lower-index wins ties, matches top_k)
__device__ __forceinline__ void insert32(float (&dist)[KF], int (&idx)[KF],
                                         float cd, int ci) {
#pragma unroll
    for (int k = 0; k < KF; k++) {
        bool p = cd < dist[k];
        float nd = p ? cd : dist[k];
        float xd = p ? dist[k] : cd;
        int   ni = p ? ci : idx[k];
        int   xi = p ? idx[k] : ci;
        dist[k] = nd; cd = xd;
        idx[k]  = ni; ci = xi;
    }
}

// ---------------- MLP stage 1 ----------------
__global__ void k_mlp1(const float* __restrict__ feat,
                       const float* __restrict__ W1,
                       const float* __restrict__ b1) {
    __shared__ float sW[C_IN * H_DIM];
    __shared__ float sb[H_DIM];
    __shared__ float s_sum[H_DIM], s_sq[H_DIM];
    int t = threadIdx.x;
    for (int i = t; i < C_IN * H_DIM; i += blockDim.x) sW[i] = W1[i];
    if (t < H_DIM) { sb[t] = b1[t]; s_sum[t] = 0.0f; s_sq[t] = 0.0f; }
    __syncthreads();

    int row = blockIdx.x * blockDim.x + t;
    float f[C_IN];
#pragma unroll
    for (int c = 0; c < C_IN; c++) f[c] = feat[row * C_IN + c];

    int lane = t & 31;
#pragma unroll
    for (int h = 0; h < H_DIM; h++) {
        float a = sb[h];
#pragma unroll
        for (int c = 0; c < C_IN; c++) a = fmaf(f[c], sW[c * H_DIM + h], a);
        g_z1[h * N_PTS + row] = a;
        float v = a, v2 = a * a;
#pragma unroll
        for (int o = 16; o; o >>= 1) {
            v  += __shfl_down_sync(0xffffffffu, v,  o);
            v2 += __shfl_down_sync(0xffffffffu, v2, o);
        }
        if (lane == 0) { atomicAdd(&s_sum[h], v); atomicAdd(&s_sq[h], v2); }
    }
    __syncthreads();
    if (t < H_DIM) {
        atomicAdd(&g_bn[t], s_sum[t]);
        atomicAdd(&g_bn[H_DIM + t], s_sq[t]);
    }
}

// ---------------- MLP stage 2 ----------------
__global__ void k_mlp2(const float* __restrict__ W2,
                       const float* __restrict__ b2,
                       const float* __restrict__ g1,
                       const float* __restrict__ be1) {
    __shared__ float sW[H_DIM * H_DIM];
    __shared__ float s_mu[H_DIM], s_rs[H_DIM], s_g[H_DIM], s_be[H_DIM], s_b2[H_DIM];
    __shared__ float s_sum[H_DIM], s_sq[H_DIM];
    int t = threadIdx.x;
    for (int i = t; i < H_DIM * H_DIM; i += blockDim.x) sW[i] = W2[i];
    if (t < H_DIM) {
        float mu  = g_bn[t] * (1.0f / N_PTS);
        float var = g_bn[H_DIM + t] * (1.0f / N_PTS) - mu * mu;
        s_mu[t] = mu;
        s_rs[t] = rsqrtf(var + 1e-5f);
        s_g[t] = g1[t]; s_be[t] = be1[t]; s_b2[t] = b2[t];
        s_sum[t] = 0.0f; s_sq[t] = 0.0f;
    }
    __syncthreads();

    int row = blockIdx.x * blockDim.x + t;
    float h1[H_DIM];
#pragma unroll
    for (int h = 0; h < H_DIM; h++) {
        float x = g_z1[h * N_PTS + row];
        x = s_g[h] * (x - s_mu[h]) * s_rs[h] + s_be[h];
        h1[h] = gelu_exact(x);
    }

    int lane = t & 31;
    for (int j = 0; j < H_DIM; j++) {
        float acc = s_b2[j];
#pragma unroll
        for (int h = 0; h < H_DIM; h++) acc = fmaf(h1[h], sW[h * H_DIM + j], acc);
        g_z2[j * N_PTS + row] = acc;
        float v = acc, v2 = acc * acc;
#pragma unroll
        for (int o = 16; o; o >>= 1) {
            v  += __shfl_down_sync(0xffffffffu, v,  o);
            v2 += __shfl_down_sync(0xffffffffu, v2, o);
        }
        if (lane == 0) { atomicAdd(&s_sum[j], v); atomicAdd(&s_sq[j], v2); }
    }
    __syncthreads();
    if (t < H_DIM) {
        atomicAdd(&g_bn[2 * H_DIM + t], s_sum[t]);
        atomicAdd(&g_bn[3 * H_DIM + t], s_sq[t]);
    }
}

// ---------------- MLP stage 3 ----------------
__global__ void k_mlp3(const float* __restrict__ W3,
                       const float* __restrict__ b3,
                       const float* __restrict__ g2,
                       const float* __restrict__ be2) {
    __shared__ float s_mu[H_DIM], s_rs[H_DIM], s_g[H_DIM], s_be[H_DIM], s_w3[H_DIM];
    __shared__ float s_b3;
    int t = threadIdx.x;
    if (t < H_DIM) {
        float mu  = g_bn[2 * H_DIM + t] * (1.0f / N_PTS);
        float var = g_bn[3 * H_DIM + t] * (1.0f / N_PTS) - mu * mu;
        s_mu[t] = mu;
        s_rs[t] = rsqrtf(var + 1e-5f);
        s_g[t] = g2[t]; s_be[t] = be2[t]; s_w3[t] = W3[t];
    }
    if (t == 0) s_b3 = b3[0];
    __syncthreads();

    int row = blockIdx.x * blockDim.x + t;
    float acc = s_b3;
#pragma unroll
    for (int h = 0; h < H_DIM; h++) {
        float x = g_z2[h * N_PTS + row];
        x = s_g[h] * (x - s_mu[h]) * s_rs[h] + s_be[h];
        x = gelu_exact(x);
        acc = fmaf(x, s_w3[h], acc);
    }
    g_s[row] = 1.0f / (1.0f + expf(-acc));
}

// ---------------- KNN (single pass, buffered top-32, v-space) + fused loss ----
// v = ||c||^2 - 2 q.c = d2 - ||q||^2 : per-query monotone in d2 (reference's own
// selection formula). Exact diff-form d2 recomputed for the 16 near neighbors.
__global__ void __launch_bounds__(KNN_BLK, 4)
k_knn(const float* __restrict__ coords) {
    __shared__ float4 sc[TILE];
    __shared__ float s_red[4 * 5];

    int t = threadIdx.x;
    int qi = blockIdx.x * KNN_BLK + t;
    int scene_base = qi & ~(M_PTS - 1);

    float qx = coords[qi * 3 + 0];
    float qy = coords[qi * 3 + 1];
    float qz = coords[qi * 3 + 2];
    float ax = -2.0f * qx, ay = -2.0f * qy, az = -2.0f * qz;

    float dist[KF];
    int   idx[KF];
#pragma unroll
    for (int k = 0; k < KF; k++) { dist[k] = FLT_MAX; idx[k] = 0; }

    float buf_d[CAP];
    int   buf_i[CAP];
    int   cnt = 0;
    float tau = FLT_MAX;
    bool  boot = true;

    for (int tile = 0; tile < M_PTS; tile += TILE) {
        for (int i = t; i < TILE; i += KNN_BLK) {
            int g = (scene_base + tile + i) * 3;
            float x = coords[g], y = coords[g + 1], z = coords[g + 2];
            sc[i] = make_float4(x, y, z, fmaf(x, x, fmaf(y, y, z * z)));
        }
        __syncthreads();

        for (int chunk = 0; chunk < TILE; chunk += 32) {
            if (boot) {
#pragma unroll
                for (int cc = 0; cc < 32; cc++) {
                    float4 p = sc[cc];
                    float v = fmaf(ax, p.x, fmaf(ay, p.y, fmaf(az, p.z, p.w)));
                    insert32(dist, idx, v, scene_base + cc);
                }
                boot = false;
                tau = dist[KF - 1];
            } else {
#pragma unroll
                for (int cc = 0; cc < 32; cc++) {
                    float4 p = sc[chunk + cc];
                    float v = fmaf(ax, p.x, fmaf(ay, p.y, fmaf(az, p.z, p.w)));
                    if (v < tau) {
                        buf_d[cnt] = v;
                        buf_i[cnt] = scene_base + tile + chunk + cc;
                        cnt++;
                    }
                }
                if (__any_sync(0xffffffffu, cnt > CAP - 32)) {
                    for (int j = 0; j < cnt; j++) {
                        float cd = buf_d[j];
                        if (cd < dist[KF - 1]) insert32(dist, idx, cd, buf_i[j]);
                    }
                    cnt = 0;
                    tau = dist[KF - 1];
                }
            }
        }
        __syncthreads();
    }
    for (int j = 0; j < cnt; j++) {
        float cd = buf_d[j];
        if (cd < dist[KF - 1]) insert32(dist, idx, cd, buf_i[j]);
    }

    // ---- fused loss (exact diff-form d2 for near neighbors) ----
    float si = g_s[qi];
    float num = 0.0f, den = 0.0f, lp = 0.0f, ln_ = 0.0f, nm = 0.0f;

#pragma unroll
    for (int k = 0; k < KN; k++) {
        int j = idx[k];
        float sj = g_s[j];
        float ad = fabsf(si - sj);
        float dx = qx - coords[j * 3 + 0];
        float dy = qy - coords[j * 3 + 1];
        float dz = qz - coords[j * 3 + 2];
        float d2 = fmaf(dz, dz, fmaf(dy, dy, dx * dx));
        float d  = sqrtf(fmaxf(d2, 1e-24f));
        float w  = expf(-d * 10.0f);                   // 1 / T_LOC
        num = fmaf(w * ad, ad, num);
        den += w;
        float simp = 1.0f - ad;
        float sg = 1.0f / (1.0f + expf(-2.0f * simp)); // / T_CON
        lp += logf(sg + 1e-8f);
        if (k < KS) nm += sj;
    }
#pragma unroll
    for (int k = KN; k < KF; k++) {
        float sj = g_s[idx[k]];
        float ad = fabsf(si - sj);
        float simn = 1.0f - ad;
        float sg = 1.0f / (1.0f + expf(-2.0f * simn));
        ln_ += logf(1.0f - sg + 1e-8f);
    }
    nm *= (1.0f / KS);
    float sm = (si - nm) * (si - nm);

    int lane = t & 31, wid = t >> 5;
    float v0 = num, v1 = den, v2 = lp, v3 = ln_, v4 = sm;
#pragma unroll
    for (int o = 16; o; o >>= 1) {
        v0 += __shfl_down_sync(0xffffffffu, v0, o);
        v1 += __shfl_down_sync(0xffffffffu, v1, o);
        v2 += __shfl_down_sync(0xffffffffu, v2, o);
        v3 += __shfl_down_sync(0xffffffffu, v3, o);
        v4 += __shfl_down_sync(0xffffffffu, v4, o);
    }
    if (lane == 0) {
        s_red[wid * 5 + 0] = v0; s_red[wid * 5 + 1] = v1;
        s_red[wid * 5 + 2] = v2; s_red[wid * 5 + 3] = v3;
        s_red[wid * 5 + 4] = v4;
    }
    __syncthreads();
    if (t == 0) {
        double a0 = 0, a1 = 0, a2 = 0, a3 = 0, a4 = 0;
#pragma unroll
        for (int w = 0; w < 4; w++) {
            a0 += (double)s_red[w * 5 + 0];
            a1 += (double)s_red[w * 5 + 1];
            a2 += (double)s_red[w * 5 + 2];
            a3 += (double)s_red[w * 5 + 3];
            a4 += (double)s_red[w * 5 + 4];
        }
        atomicAdd(&g_acc[0], a0);
        atomicAdd(&g_acc[1], a1);
        atomicAdd(&g_acc[2], a2);
        atomicAdd(&g_acc[3], a3);
        atomicAdd(&g_acc[4], a4);
    }
}

__global__ void k_fin(float* __restrict__ out) {
    if (threadIdx.x == 0) {
        double loc = g_acc[0] / fmax(g_acc[1], 1e-8);
        double inv = 1.0 / ((double)N_PTS * (double)KN);
        double pos = -g_acc[2] * inv;
        double neg = -g_acc[3] * inv;
        double sm  = g_acc[4] / (double)N_PTS;
        out[0] = (float)(loc + 0.5 * (pos + neg) + 0.2 * sm);
    }
}

// ---------------- launch ----------------
extern "C" void kernel_launch(void* const* d_in, const int* in_sizes, int n_in,
                              void* d_out, int out_size) {
    const float* feat   = (const float*)d_in[0];
    const float* coords = (const float*)d_in[1];
    const float* W1 = (const float*)d_in[2];
    const float* b1 = (const float*)d_in[3];
    const float* g1 = (const float*)d_in[4];
    const float* be1 = (const float*)d_in[5];
    const float* W2 = (const float*)d_in[6];
    const float* b2 = (const float*)d_in[7];
    const float* g2 = (const float*)d_in[8];
    const float* be2 = (const float*)d_in[9];
    const float* W3 = (const float*)d_in[10];
    const float* b3 = (const float*)d_in[11];
    float* out = (float*)d_out;

    k_zero<<<1, 256>>>();
    k_mlp1<<<N_PTS / 256, 256>>>(feat, W1, b1);
    k_mlp2<<<N_PTS / 256, 256>>>(W2, b2, g1, be1);
    k_mlp3<<<N_PTS / 256, 256>>>(W3, b3, g2, be2);
    k_knn<<<N_PTS / KNN_BLK, KNN_BLK>>>(coords);
    k_fin<<<1, 1>>>(out);
}